// round 6
// baseline (speedup 1.0000x reference)
#include <cuda_runtime.h>
#include <stdint.h>

#define N_STEPS 50

// Output layout (flattened tuple, row-major, float32):
//   slot0 = Xn history [32,50,64,8]      @ 0          (post-sample state)
//   slot1 = En history [32,50,64,64,5]   @ 819200     (post-sample state)
//   slot2 = Xc history [32,50,64,8]      @ 33587200   (pre-step state)
//   slot3 = Ec history [32,50,64,64,5]   @ 34406400   (pre-step state)
#define OFF_EN  819200
#define OFF_XC  33587200
#define OFF_EC  34406400

// Per-step derived keys (partitionable split) + precomputed log-prob tables.
__device__ uint2 g_kx[N_STEPS];
__device__ uint2 g_ke[N_STEPS];
__device__ float g_lqe[N_STEPS * 25];   // [k][l][c], D=5
__device__ float g_lqx[N_STEPS * 64];   // [k][l][c], D=8

// ---------------- Threefry-2x32 (JAX-exact: 20 rounds, 5 key injections) ----
__device__ __forceinline__ void tf2x32(uint32_t k0, uint32_t k1,
                                       uint32_t x0, uint32_t x1,
                                       uint32_t& o0, uint32_t& o1) {
    uint32_t ks2 = k0 ^ k1 ^ 0x1BD11BDAu;
    x0 += k0; x1 += k1;
#define TF_R(r) { x0 += x1; x1 = __funnelshift_l(x1, x1, (r)); x1 ^= x0; }
    TF_R(13) TF_R(15) TF_R(26) TF_R(6)
    x0 += k1;  x1 += ks2 + 1u;
    TF_R(17) TF_R(29) TF_R(16) TF_R(24)
    x0 += ks2; x1 += k0 + 2u;
    TF_R(13) TF_R(15) TF_R(26) TF_R(6)
    x0 += k0;  x1 += k1 + 3u;
    TF_R(17) TF_R(29) TF_R(16) TF_R(24)
    x0 += k1;  x1 += ks2 + 4u;
    TF_R(13) TF_R(15) TF_R(26) TF_R(6)
    x0 += ks2; x1 += k0 + 5u;
#undef TF_R
    o0 = x0; o1 = x1;
}

// Partitionable random_bits(32): element i -> XOR of both cipher words of
// block (hi,lo) = (0, i).
__device__ __forceinline__ uint32_t jax_bits32(uint2 key, uint32_t idx) {
    uint32_t o0, o1;
    tf2x32(key.x, key.y, 0u, idx, o0, o1);
    return o0 ^ o1;
}

// JAX gumbel from raw bits (bit-exact op sequence).
__device__ __forceinline__ float gumbel_from_bits(uint32_t bits) {
    const float TINY = 1.17549435082228751e-38f;
    float u = __uint_as_float((bits >> 9) | 0x3f800000u) - 1.0f;
    u = u + TINY;
    u = fmaxf(TINY, u);
    return -logf(-logf(u));
}

// ------- init: per-step keys (fold_in + partitionable split) + logq tables ---
template <int D>
__device__ __forceinline__ void make_logq(const float* __restrict__ W,
                                          float gamma, float* __restrict__ dst) {
    for (int l = 0; l < D; l++) {
        const float* row = W + l * D;
        float p[D];
        float m = row[0];
        for (int c = 1; c < D; c++) m = fmaxf(m, row[c]);
        float s = 0.0f;
        for (int c = 0; c < D; c++) { p[c] = expf(row[c] - m); s += p[c]; }
        for (int c = 0; c < D; c++) p[c] = (p[c] / s) * gamma;
        p[l] = 0.0f;
        float s2 = 0.0f;
        for (int c = 0; c < D; c++) s2 += p[c];
        p[l] = fmaxf(1.0f - s2, 0.0f);
        float t = 0.0f;
        for (int c = 0; c < D; c++) t += p[c];
        for (int c = 0; c < D; c++) dst[l * D + c] = logf(p[c] / t);
    }
}

__global__ void init_kernel(const float* __restrict__ gammas,
                            const float* __restrict__ Wx,
                            const float* __restrict__ We) {
    int k = threadIdx.x;
    if (k >= N_STEPS) return;
    uint32_t f0, f1;
    tf2x32(0u, 42u, 0u, (uint32_t)k, f0, f1);        // fold_in(key(42), k)
    uint32_t a0, a1, b0, b1;
    tf2x32(f0, f1, 0u, 0u, a0, a1);                  // split key[0]
    tf2x32(f0, f1, 0u, 1u, b0, b1);                  // split key[1]
    g_kx[k] = make_uint2(a0, a1);
    g_ke[k] = make_uint2(b0, b1);

    float gamma = gammas[k];
    make_logq<5>(We, gamma, &g_lqe[k * 25]);
    make_logq<8>(Wx, gamma, &g_lqx[k * 64]);
}

// node_mask dtype detection (bool8 / int32 / float32).
__device__ __forceinline__ int detect_mask_mode(const void* p) {
    const unsigned char* u = (const unsigned char*)p;
    if (u[1] == 1) return 0;
    if (((const int*)p)[0] == 1) return 1;
    return 2;
}
__device__ __forceinline__ bool mask_val(const void* p, int mode, int idx) {
    if (mode == 0) return ((const unsigned char*)p)[idx] != 0;
    if (mode == 1) return ((const int*)p)[idx] != 0;
    return ((const float*)p)[idx] != 0.0f;
}

// ---------------------------- main kernel -----------------------------------
// Blocks 0..511: edge chains (one thread per (b,i,j); 131072 threads)
// Blocks 512..519: node chains (one thread per (b,i); 2048 threads)
// Occupancy is thread-count-capped at ~4 blocks/SM -> 64 regs/thread are free.
__global__ __launch_bounds__(256, 4)
void langevin_main(const float* __restrict__ X, const float* __restrict__ E,
                   const void* __restrict__ maskp,
                   float* __restrict__ out) {
    __shared__ uint2 sKey[N_STEPS];
    __shared__ float sLq[N_STEPS * 64];
    __shared__ int sMode;

    const bool edge = blockIdx.x < 512;
    if (edge) {
        for (int t = threadIdx.x; t < N_STEPS; t += 256) sKey[t] = g_ke[t];
        for (int t = threadIdx.x; t < N_STEPS * 25; t += 256) sLq[t] = g_lqe[t];
    } else {
        for (int t = threadIdx.x; t < N_STEPS; t += 256) sKey[t] = g_kx[t];
        for (int t = threadIdx.x; t < N_STEPS * 64; t += 256) sLq[t] = g_lqx[t];
    }
    if (threadIdx.x == 0) sMode = detect_mask_mode(maskp);
    __syncthreads();
    const int mode = sMode;

    if (edge) {
        int tid = blockIdx.x * 256 + threadIdx.x;      // 0..131071
        int b = tid >> 12;
        int ij = tid & 4095;
        int i = ij >> 6, j = ij & 63;
        bool valid = (i != j) && mask_val(maskp, mode, b * 64 + i)
                              && mask_val(maskp, mode, b * 64 + j);
        int lo = (i < j) ? i : j;
        int hi = (i < j) ? j : i;
        uint32_t gbase = (uint32_t)(((b * 64 + lo) * 64 + hi) * 5);

        float in[5];
        const float* ep = E + ((size_t)b * 4096 + ij) * 5;
#pragma unroll
        for (int c = 0; c < 5; c++) in[c] = ep[c];

        // post-sample (En) -> slot1; pre-step (Ec) -> slot3
        float* postE = out + OFF_EN + (size_t)b * 50 * 20480 + (size_t)ij * 5;
        float* preE  = out + OFF_EC + (size_t)b * 50 * 20480 + (size_t)ij * 5;

        if (valid) {
            int l = 0;
            float bv = in[0];
#pragma unroll
            for (int c = 1; c < 5; c++) if (in[c] > bv) { bv = in[c]; l = c; }
            // k=0 pre-step store is the raw input (peeled out of the loop)
#pragma unroll
            for (int c = 0; c < 5; c++) preE[c] = in[c];

            // 10 batches of 5 steps: RNG for the whole batch first (25
            // independent cipher+gumbel chains -> deep ILP), then 5 quick
            // serial resolve+store tails.
#pragma unroll 1
            for (int kb = 0; kb < N_STEPS; kb += 5) {
                float g[5][5];
#pragma unroll
                for (int s = 0; s < 5; s++) {
                    uint2 key = sKey[kb + s];
#pragma unroll
                    for (int c = 0; c < 5; c++)
                        g[s][c] = gumbel_from_bits(jax_bits32(key, gbase + c));
                }
#pragma unroll
                for (int s = 0; s < 5; s++) {
                    int k = kb + s;
                    float* pp = preE  + (size_t)k * 20480;
                    float* sp = postE + (size_t)k * 20480;
                    if (k != 0) {
#pragma unroll
                        for (int c = 0; c < 5; c++) pp[c] = (c == l) ? 1.0f : 0.0f;
                    }
                    const float* lq = &sLq[k * 25 + l * 5];
                    float best = lq[0] + g[s][0];
                    int bi = 0;
#pragma unroll
                    for (int c = 1; c < 5; c++) {
                        float sc = lq[c] + g[s][c];
                        if (sc > best) { best = sc; bi = c; }
                    }
                    l = bi;
#pragma unroll
                    for (int c = 0; c < 5; c++) sp[c] = (c == l) ? 1.0f : 0.0f;
                }
            }
        } else {
            // masked or diagonal: pre = input at k=0 else 0; post = 0 always
#pragma unroll 2
            for (int k = 0; k < N_STEPS; k++) {
                float* pp = preE  + (size_t)k * 20480;
                float* sp = postE + (size_t)k * 20480;
#pragma unroll
                for (int c = 0; c < 5; c++) pp[c] = (k == 0) ? in[c] : 0.0f;
#pragma unroll
                for (int c = 0; c < 5; c++) sp[c] = 0.0f;
            }
        }
    } else {
        int t = (blockIdx.x - 512) * 256 + threadIdx.x;  // 0..2047
        int b = t >> 6, i = t & 63;
        bool valid = mask_val(maskp, mode, b * 64 + i);
        uint32_t gbase = (uint32_t)((b * 64 + i) * 8);

        float in[8];
        const float* xp = X + (size_t)(b * 64 + i) * 8;
#pragma unroll
        for (int c = 0; c < 8; c++) in[c] = xp[c];

        // post-sample (Xn) -> slot0; pre-step (Xc) -> slot2
        float* postX = out + (size_t)b * 50 * 512 + (size_t)i * 8;
        float* preX  = out + OFF_XC + (size_t)b * 50 * 512 + (size_t)i * 8;

        if (valid) {
            int l = 0;
            float bv = in[0];
#pragma unroll
            for (int c = 1; c < 8; c++) if (in[c] > bv) { bv = in[c]; l = c; }
#pragma unroll
            for (int c = 0; c < 8; c++) preX[c] = in[c];

            // 25 batches of 2 steps (16 gumbels in flight).
#pragma unroll 1
            for (int kb = 0; kb < N_STEPS; kb += 2) {
                float g[2][8];
#pragma unroll
                for (int s = 0; s < 2; s++) {
                    uint2 key = sKey[kb + s];
#pragma unroll
                    for (int c = 0; c < 8; c++)
                        g[s][c] = gumbel_from_bits(jax_bits32(key, gbase + c));
                }
#pragma unroll
                for (int s = 0; s < 2; s++) {
                    int k = kb + s;
                    float* pp = preX  + (size_t)k * 512;
                    float* sp = postX + (size_t)k * 512;
                    if (k != 0) {
#pragma unroll
                        for (int c = 0; c < 8; c++) pp[c] = (c == l) ? 1.0f : 0.0f;
                    }
                    const float* lq = &sLq[k * 64 + l * 8];
                    float best = lq[0] + g[s][0];
                    int bi = 0;
#pragma unroll
                    for (int c = 1; c < 8; c++) {
                        float sc = lq[c] + g[s][c];
                        if (sc > best) { best = sc; bi = c; }
                    }
                    l = bi;
#pragma unroll
                    for (int c = 0; c < 8; c++) sp[c] = (c == l) ? 1.0f : 0.0f;
                }
            }
        } else {
#pragma unroll 2
            for (int k = 0; k < N_STEPS; k++) {
                float* pp = preX  + (size_t)k * 512;
                float* sp = postX + (size_t)k * 512;
#pragma unroll
                for (int c = 0; c < 8; c++) pp[c] = (k == 0) ? in[c] : 0.0f;
#pragma unroll
                for (int c = 0; c < 8; c++) sp[c] = 0.0f;
            }
        }
    }
}

extern "C" void kernel_launch(void* const* d_in, const int* in_sizes, int n_in,
                              void* d_out, int out_size) {
    (void)in_sizes; (void)n_in; (void)out_size;
    const float* X      = (const float*)d_in[0];
    const float* E      = (const float*)d_in[1];
    const void*  maskp  = d_in[2];
    const float* gammas = (const float*)d_in[3];
    const float* Wx     = (const float*)d_in[4];
    const float* We     = (const float*)d_in[5];

    init_kernel<<<1, 64>>>(gammas, Wx, We);
    langevin_main<<<520, 256>>>(X, E, maskp, (float*)d_out);
}

// round 12
// speedup vs baseline: 1.3814x; 1.3814x over previous
#include <cuda_runtime.h>
#include <stdint.h>

#define N_STEPS 50

// Output layout (flattened tuple, row-major, float32):
//   slot0 = Xn history [32,50,64,8]      @ 0          (post-sample state)
//   slot1 = En history [32,50,64,64,5]   @ 819200     (post-sample state)
//   slot2 = Xc history [32,50,64,8]      @ 33587200   (pre-step state)
//   slot3 = Ec history [32,50,64,64,5]   @ 34406400   (pre-step state)
#define OFF_EN  819200
#define OFF_XC  33587200
#define OFF_EC  34406400

// Per-step derived keys (partitionable split) + precomputed log-prob tables.
__device__ uint2 g_kx[N_STEPS];
__device__ uint2 g_ke[N_STEPS];
__device__ float g_lqe[N_STEPS * 25];   // [k][l][c], D=5
__device__ float g_lqx[N_STEPS * 64];   // [k][l][c], D=8

// Tile-pair table: 4 diagonal tiles then 6 off-diagonal (TI < TJ).
__constant__ int c_TPI[10] = {0, 1, 2, 3, 0, 0, 0, 1, 1, 2};
__constant__ int c_TPJ[10] = {0, 1, 2, 3, 1, 2, 3, 2, 3, 3};

// ---------------- Threefry-2x32 (JAX-exact: 20 rounds, 5 key injections) ----
__device__ __forceinline__ void tf2x32(uint32_t k0, uint32_t k1,
                                       uint32_t x0, uint32_t x1,
                                       uint32_t& o0, uint32_t& o1) {
    uint32_t ks2 = k0 ^ k1 ^ 0x1BD11BDAu;
    x0 += k0; x1 += k1;
#define TF_R(r) { x0 += x1; x1 = __funnelshift_l(x1, x1, (r)); x1 ^= x0; }
    TF_R(13) TF_R(15) TF_R(26) TF_R(6)
    x0 += k1;  x1 += ks2 + 1u;
    TF_R(17) TF_R(29) TF_R(16) TF_R(24)
    x0 += ks2; x1 += k0 + 2u;
    TF_R(13) TF_R(15) TF_R(26) TF_R(6)
    x0 += k0;  x1 += k1 + 3u;
    TF_R(17) TF_R(29) TF_R(16) TF_R(24)
    x0 += k1;  x1 += ks2 + 4u;
    TF_R(13) TF_R(15) TF_R(26) TF_R(6)
    x0 += ks2; x1 += k0 + 5u;
#undef TF_R
    o0 = x0; o1 = x1;
}

// Partitionable random_bits(32): element i -> XOR of both cipher words of
// block (hi,lo) = (0, i).
__device__ __forceinline__ uint32_t jax_bits32(uint2 key, uint32_t idx) {
    uint32_t o0, o1;
    tf2x32(key.x, key.y, 0u, idx, o0, o1);
    return o0 ^ o1;
}

// JAX gumbel from raw bits (bit-exact op sequence).
__device__ __forceinline__ float gumbel_from_bits(uint32_t bits) {
    const float TINY = 1.17549435082228751e-38f;
    float u = __uint_as_float((bits >> 9) | 0x3f800000u) - 1.0f;
    u = u + TINY;
    u = fmaxf(TINY, u);
    return -logf(-logf(u));
}

// ------- init: per-step keys (fold_in + partitionable split) + logq tables ---
template <int D>
__device__ __forceinline__ void make_logq(const float* __restrict__ W,
                                          float gamma, float* __restrict__ dst) {
    for (int l = 0; l < D; l++) {
        const float* row = W + l * D;
        float p[D];
        float m = row[0];
        for (int c = 1; c < D; c++) m = fmaxf(m, row[c]);
        float s = 0.0f;
        for (int c = 0; c < D; c++) { p[c] = expf(row[c] - m); s += p[c]; }
        for (int c = 0; c < D; c++) p[c] = (p[c] / s) * gamma;
        p[l] = 0.0f;
        float s2 = 0.0f;
        for (int c = 0; c < D; c++) s2 += p[c];
        p[l] = fmaxf(1.0f - s2, 0.0f);
        float t = 0.0f;
        for (int c = 0; c < D; c++) t += p[c];
        for (int c = 0; c < D; c++) dst[l * D + c] = logf(p[c] / t);
    }
}

__global__ void init_kernel(const float* __restrict__ gammas,
                            const float* __restrict__ Wx,
                            const float* __restrict__ We) {
    int k = threadIdx.x;
    if (k >= N_STEPS) return;
    uint32_t f0, f1;
    tf2x32(0u, 42u, 0u, (uint32_t)k, f0, f1);        // fold_in(key(42), k)
    uint32_t a0, a1, b0, b1;
    tf2x32(f0, f1, 0u, 0u, a0, a1);                  // split key[0]
    tf2x32(f0, f1, 0u, 1u, b0, b1);                  // split key[1]
    g_kx[k] = make_uint2(a0, a1);
    g_ke[k] = make_uint2(b0, b1);

    float gamma = gammas[k];
    make_logq<5>(We, gamma, &g_lqe[k * 25]);
    make_logq<8>(Wx, gamma, &g_lqx[k * 64]);
}

// node_mask dtype detection (bool8 / int32 / float32).
__device__ __forceinline__ int detect_mask_mode(const void* p) {
    const unsigned char* u = (const unsigned char*)p;
    if (u[1] == 1) return 0;
    if (((const int*)p)[0] == 1) return 1;
    return 2;
}
__device__ __forceinline__ bool mask_val(const void* p, int mode, int idx) {
    if (mode == 0) return ((const unsigned char*)p)[idx] != 0;
    if (mode == 1) return ((const int*)p)[idx] != 0;
    return ((const float*)p)[idx] != 0.0f;
}

// ---------------------------- main kernel -----------------------------------
// Blocks 0..319: edge tiles. block = (b, tile-pair). Each thread owns ONE
//   unordered pair chain (symmetry: (i,j) and (j,i) are identical chains),
//   records a 1-byte label per step in SMEM, then a coalesced float4 copy-out
//   expands labels to one-hot for both orientations and both output arrays.
// Blocks 320..327: node chains (one thread per (b,i); 2048 threads).
__global__ __launch_bounds__(256, 4)
void langevin_main(const float* __restrict__ X, const float* __restrict__ E,
                   const void* __restrict__ maskp,
                   float* __restrict__ out) {
    __shared__ uint2 sKey[N_STEPS];
    __shared__ float sLq[N_STEPS * 64];
    __shared__ unsigned char sLab[N_STEPS * 256];   // [k][il][jl]
    __shared__ int sMode;

    const bool edge = blockIdx.x < 320;
    if (edge) {
        for (int t = threadIdx.x; t < N_STEPS; t += 256) sKey[t] = g_ke[t];
        for (int t = threadIdx.x; t < N_STEPS * 25; t += 256) sLq[t] = g_lqe[t];
    } else {
        for (int t = threadIdx.x; t < N_STEPS; t += 256) sKey[t] = g_kx[t];
        for (int t = threadIdx.x; t < N_STEPS * 64; t += 256) sLq[t] = g_lqx[t];
    }
    if (threadIdx.x == 0) sMode = detect_mask_mode(maskp);
    __syncthreads();
    const int mode = sMode;

    if (edge) {
        int e = blockIdx.x;
        int b = e / 10;
        int tp = e - b * 10;
        const int I0 = c_TPI[tp] * 16, J0 = c_TPJ[tp] * 16;
        const bool diag = tp < 4;
        const int il = threadIdx.x >> 4, jl = threadIdx.x & 15;
        const int gi = I0 + il, gj = J0 + jl;         // gi < gj for all pairs
        const bool pair  = diag ? (il < jl) : true;   // owns a chain
        const bool owner = diag ? (il <= jl) : true;  // writes label cell(s)
        const bool valid = pair && mask_val(maskp, mode, b * 64 + gi)
                                && mask_val(maskp, mode, b * 64 + gj);
        const int lo0 = il * 16 + jl;
        const int lo1 = jl * 16 + il;

        if (valid) {
            uint32_t gbase = (uint32_t)(((b * 64 + gi) * 64 + gj) * 5);
            const float* ep = E + ((size_t)(b * 4096) + gi * 64 + gj) * 5;
            int l = 0;
            float bv = ep[0];
#pragma unroll
            for (int c = 1; c < 5; c++) { float v = ep[c]; if (v > bv) { bv = v; l = c; } }
#pragma unroll 2
            for (int k = 0; k < N_STEPS; k++) {
                uint2 key = sKey[k];
                float g[5];
#pragma unroll
                for (int c = 0; c < 5; c++)
                    g[c] = gumbel_from_bits(jax_bits32(key, gbase + c));
                const float* lq = &sLq[k * 25 + l * 5];
                float best = lq[0] + g[0];
                int bi = 0;
#pragma unroll
                for (int c = 1; c < 5; c++) {
                    float sc = lq[c] + g[c];
                    if (sc > best) { best = sc; bi = c; }
                }
                l = bi;
                sLab[k * 256 + lo0] = (unsigned char)l;
                if (diag) sLab[k * 256 + lo1] = (unsigned char)l;
            }
        } else if (owner) {
            // masked pair or diagonal cell: label 0xFF -> expands to all-zero
            for (int k = 0; k < N_STEPS; k++) {
                sLab[k * 256 + lo0] = 0xFFu;
                if (diag && il < jl) sLab[k * 256 + lo1] = 0xFFu;
            }
        }
        __syncthreads();

        // ---------------- copy-out: labels -> one-hot float4 ----------------
        // Per-batch slab bases (k-step stride is 20480 floats inside a slab).
        float* postE = out + OFF_EN + (size_t)b * (50 * 20480);
        float* preE  = out + OFF_EC + (size_t)b * (50 * 20480);
        const float* rawE = E + (size_t)b * 20480;
        const int nOr = diag ? 1 : 2;
        for (int o = 0; o < nOr; o++) {
            const int r0 = o ? J0 : I0;
            const int c0 = o ? I0 : J0;
            // intra-batch tile offset (NO b term — slab bases carry it)
            const size_t tbO = ((size_t)r0 * 64 + c0) * 5;
            // 320 float4 per 16x80-float tile; thread takes m and m+256.
            for (int mi = 0; mi < 2; mi++) {
                const int m = threadIdx.x + mi * 256;
                if (m >= 320) break;
                const int r = m / 20;           // tile row (0..15)
                const int q = m - r * 20;       // float4 within row (0..19)
                const int f0 = q * 4;
                int lofs[4], cch[4];
#pragma unroll
                for (int t = 0; t < 4; t++) {
                    int f = f0 + t;
                    int cl = f / 5;             // local column (0..15)
                    cch[t] = f - cl * 5;        // class index (0..4)
                    lofs[t] = o ? (cl * 16 + r) : (r * 16 + cl);
                }
                float* pPost = postE + tbO + (size_t)r * 320;
                float* pPre  = preE  + tbO + (size_t)r * 320;
                const float* pRaw = rawE + tbO + (size_t)r * 320;
                // pre[0] = raw input
                ((float4*)pPre)[q] = ((const float4*)pRaw)[q];
                // post[k] and pre[k+1] share one expansion of labels[k]
#pragma unroll 2
                for (int k = 0; k < N_STEPS; k++) {
                    const unsigned char* L = &sLab[k * 256];
                    float4 v;
                    v.x = (cch[0] == (int)L[lofs[0]]) ? 1.0f : 0.0f;
                    v.y = (cch[1] == (int)L[lofs[1]]) ? 1.0f : 0.0f;
                    v.z = (cch[2] == (int)L[lofs[2]]) ? 1.0f : 0.0f;
                    v.w = (cch[3] == (int)L[lofs[3]]) ? 1.0f : 0.0f;
                    ((float4*)(pPost + (size_t)k * 20480))[q] = v;
                    if (k < N_STEPS - 1)
                        ((float4*)(pPre + (size_t)(k + 1) * 20480))[q] = v;
                }
            }
        }
    } else {
        // ------------------------- node chains ------------------------------
        int t = (blockIdx.x - 320) * 256 + threadIdx.x;  // 0..2047
        int b = t >> 6, i = t & 63;
        bool valid = mask_val(maskp, mode, b * 64 + i);
        uint32_t gbase = (uint32_t)((b * 64 + i) * 8);

        float in[8];
        const float* xp = X + (size_t)(b * 64 + i) * 8;
#pragma unroll
        for (int c = 0; c < 8; c++) in[c] = xp[c];

        float* postX = out + (size_t)b * 50 * 512 + (size_t)i * 8;
        float* preX  = out + OFF_XC + (size_t)b * 50 * 512 + (size_t)i * 8;

        if (valid) {
            int l = 0;
            float bv = in[0];
#pragma unroll
            for (int c = 1; c < 8; c++) if (in[c] > bv) { bv = in[c]; l = c; }
#pragma unroll 1
            for (int k = 0; k < N_STEPS; k++) {
                float* pp = preX  + (size_t)k * 512;
                float* sp = postX + (size_t)k * 512;
                if (k == 0) {
#pragma unroll
                    for (int c = 0; c < 8; c++) pp[c] = in[c];
                } else {
#pragma unroll
                    for (int c = 0; c < 8; c++) pp[c] = (c == l) ? 1.0f : 0.0f;
                }
                uint2 key = sKey[k];
                const float* lq = &sLq[k * 64 + l * 8];
                float best = 0.0f;
                int bi = 0;
#pragma unroll
                for (int c = 0; c < 8; c++) {
                    float g = gumbel_from_bits(jax_bits32(key, gbase + c));
                    float sc = lq[c] + g;
                    if (c == 0) best = sc;
                    else if (sc > best) { best = sc; bi = c; }
                }
                l = bi;
#pragma unroll
                for (int c = 0; c < 8; c++) sp[c] = (c == l) ? 1.0f : 0.0f;
            }
        } else {
#pragma unroll 2
            for (int k = 0; k < N_STEPS; k++) {
                float* pp = preX  + (size_t)k * 512;
                float* sp = postX + (size_t)k * 512;
#pragma unroll
                for (int c = 0; c < 8; c++) pp[c] = (k == 0) ? in[c] : 0.0f;
#pragma unroll
                for (int c = 0; c < 8; c++) sp[c] = 0.0f;
            }
        }
    }
}

extern "C" void kernel_launch(void* const* d_in, const int* in_sizes, int n_in,
                              void* d_out, int out_size) {
    (void)in_sizes; (void)n_in; (void)out_size;
    const float* X      = (const float*)d_in[0];
    const float* E      = (const float*)d_in[1];
    const void*  maskp  = d_in[2];
    const float* gammas = (const float*)d_in[3];
    const float* Wx     = (const float*)d_in[4];
    const float* We     = (const float*)d_in[5];

    init_kernel<<<1, 64>>>(gammas, Wx, We);
    // 320 edge tile blocks + 8 node blocks
    langevin_main<<<328, 256>>>(X, E, maskp, (float*)d_out);
}

// round 13
// speedup vs baseline: 1.4976x; 1.0842x over previous
#include <cuda_runtime.h>
#include <stdint.h>

#define N_STEPS 50

// Output layout (flattened tuple, row-major, float32):
//   slot0 = Xn history [32,50,64,8]      @ 0          (post-sample state)
//   slot1 = En history [32,50,64,64,5]   @ 819200     (post-sample state)
//   slot2 = Xc history [32,50,64,8]      @ 33587200   (pre-step state)
//   slot3 = Ec history [32,50,64,64,5]   @ 34406400   (pre-step state)
#define OFF_EN  819200
#define OFF_XC  33587200
#define OFF_EC  34406400

#define N_PAIRS 2016          // 64 choose 2
#define N_EFLOAT4 8192000     // 32*50*64*80 float4 in the E post array

// Per-step derived keys (partitionable split) + precomputed log-prob tables.
__device__ uint2 g_kx[N_STEPS];
__device__ uint2 g_ke[N_STEPS];
__device__ float g_lqe[N_STEPS * 25];   // [k][l][c], D=5
__device__ float g_lqx[N_STEPS * 64];   // [k][l][c], D=8
__device__ unsigned short g_pair[N_PAIRS];            // i*64+j, i<j
__device__ unsigned char g_lab[32 * 50 * 64 * 64];    // [b][k][i][j] labels

// ---------------- Threefry-2x32 (JAX-exact: 20 rounds, 5 key injections) ----
__device__ __forceinline__ void tf2x32(uint32_t k0, uint32_t k1,
                                       uint32_t x0, uint32_t x1,
                                       uint32_t& o0, uint32_t& o1) {
    uint32_t ks2 = k0 ^ k1 ^ 0x1BD11BDAu;
    x0 += k0; x1 += k1;
#define TF_R(r) { x0 += x1; x1 = __funnelshift_l(x1, x1, (r)); x1 ^= x0; }
    TF_R(13) TF_R(15) TF_R(26) TF_R(6)
    x0 += k1;  x1 += ks2 + 1u;
    TF_R(17) TF_R(29) TF_R(16) TF_R(24)
    x0 += ks2; x1 += k0 + 2u;
    TF_R(13) TF_R(15) TF_R(26) TF_R(6)
    x0 += k0;  x1 += k1 + 3u;
    TF_R(17) TF_R(29) TF_R(16) TF_R(24)
    x0 += k1;  x1 += ks2 + 4u;
    TF_R(13) TF_R(15) TF_R(26) TF_R(6)
    x0 += ks2; x1 += k0 + 5u;
#undef TF_R
    o0 = x0; o1 = x1;
}

// Partitionable random_bits(32): element i -> XOR of both cipher words.
__device__ __forceinline__ uint32_t jax_bits32(uint2 key, uint32_t idx) {
    uint32_t o0, o1;
    tf2x32(key.x, key.y, 0u, idx, o0, o1);
    return o0 ^ o1;
}

// JAX gumbel from raw bits (bit-exact op sequence).
__device__ __forceinline__ float gumbel_from_bits(uint32_t bits) {
    const float TINY = 1.17549435082228751e-38f;
    float u = __uint_as_float((bits >> 9) | 0x3f800000u) - 1.0f;
    u = u + TINY;
    u = fmaxf(TINY, u);
    return -logf(-logf(u));
}

// ------- init: per-step keys + logq tables + pair table ----------------------
template <int D>
__device__ __forceinline__ void make_logq(const float* __restrict__ W,
                                          float gamma, float* __restrict__ dst) {
    for (int l = 0; l < D; l++) {
        const float* row = W + l * D;
        float p[D];
        float m = row[0];
        for (int c = 1; c < D; c++) m = fmaxf(m, row[c]);
        float s = 0.0f;
        for (int c = 0; c < D; c++) { p[c] = expf(row[c] - m); s += p[c]; }
        for (int c = 0; c < D; c++) p[c] = (p[c] / s) * gamma;
        p[l] = 0.0f;
        float s2 = 0.0f;
        for (int c = 0; c < D; c++) s2 += p[c];
        p[l] = fmaxf(1.0f - s2, 0.0f);
        float t = 0.0f;
        for (int c = 0; c < D; c++) t += p[c];
        for (int c = 0; c < D; c++) dst[l * D + c] = logf(p[c] / t);
    }
}

__global__ void init_kernel(const float* __restrict__ gammas,
                            const float* __restrict__ Wx,
                            const float* __restrict__ We) {
    int t = threadIdx.x;
    if (t < N_STEPS) {
        uint32_t f0, f1;
        tf2x32(0u, 42u, 0u, (uint32_t)t, f0, f1);    // fold_in(key(42), k)
        uint32_t a0, a1, b0, b1;
        tf2x32(f0, f1, 0u, 0u, a0, a1);              // split key[0]
        tf2x32(f0, f1, 0u, 1u, b0, b1);              // split key[1]
        g_kx[t] = make_uint2(a0, a1);
        g_ke[t] = make_uint2(b0, b1);
        float gamma = gammas[t];
        make_logq<5>(We, gamma, &g_lqe[t * 25]);
        make_logq<8>(Wx, gamma, &g_lqx[t * 64]);
    }
    // pair table: p -> (i,j), i<j, j-fastest enumeration
    for (int p = t; p < N_PAIRS; p += blockDim.x) {
        int rem = p, i = 0;
        while (rem >= 63 - i) { rem -= 63 - i; i++; }
        int j = i + 1 + rem;
        g_pair[p] = (unsigned short)(i * 64 + j);
    }
}

// node_mask dtype detection (bool8 / int32 / float32).
__device__ __forceinline__ int detect_mask_mode(const void* p) {
    const unsigned char* u = (const unsigned char*)p;
    if (u[1] == 1) return 0;
    if (((const int*)p)[0] == 1) return 1;
    return 2;
}
__device__ __forceinline__ bool mask_val(const void* p, int mode, int idx) {
    if (mode == 0) return ((const unsigned char*)p)[idx] != 0;
    if (mode == 1) return ((const int*)p)[idx] != 0;
    return ((const float*)p)[idx] != 0.0f;
}

// --------------------------- chain kernel -----------------------------------
// Blocks 0..503: edge chains, densely packed: thread g = (b, pair p).
//   Every lane runs a chain (no diagonal/triangle waste). Labels (1 byte per
//   step) written to g_lab in both orientations; masked pairs write 0xFF.
// Blocks 504..519: node chains (one thread per (b,i)), write outputs directly.
__global__ __launch_bounds__(128, 8)
void chain_kernel(const float* __restrict__ X, const float* __restrict__ E,
                  const void* __restrict__ maskp, float* __restrict__ out) {
    __shared__ uint2 sKey[N_STEPS];
    __shared__ float sLq[N_STEPS * 64];
    __shared__ int sMode;

    const bool edge = blockIdx.x < 504;
    if (edge) {
        for (int t = threadIdx.x; t < N_STEPS; t += 128) sKey[t] = g_ke[t];
        for (int t = threadIdx.x; t < N_STEPS * 25; t += 128) sLq[t] = g_lqe[t];
    } else {
        for (int t = threadIdx.x; t < N_STEPS; t += 128) sKey[t] = g_kx[t];
        for (int t = threadIdx.x; t < N_STEPS * 64; t += 128) sLq[t] = g_lqx[t];
    }
    if (threadIdx.x == 0) sMode = detect_mask_mode(maskp);
    __syncthreads();
    const int mode = sMode;

    if (edge) {
        int g = blockIdx.x * 128 + threadIdx.x;      // 0..64511
        int b = g / N_PAIRS;
        int p = g - b * N_PAIRS;
        int ij = (int)g_pair[p];
        int i = ij >> 6, j = ij & 63;
        bool valid = mask_val(maskp, mode, b * 64 + i)
                  && mask_val(maskp, mode, b * 64 + j);
        unsigned char* lab = g_lab + (size_t)b * (50 * 4096);
        const int lo0 = i * 64 + j, lo1 = j * 64 + i;

        if (valid) {
            uint32_t gbase = (uint32_t)(((b * 64 + i) * 64 + j) * 5);
            const float* ep = E + ((size_t)(b * 4096) + ij) * 5;
            int l = 0;
            float bv = ep[0];
#pragma unroll
            for (int c = 1; c < 5; c++) { float v = ep[c]; if (v > bv) { bv = v; l = c; } }
#pragma unroll 2
            for (int k = 0; k < N_STEPS; k++) {
                uint2 key = sKey[k];
                float gg[5];
#pragma unroll
                for (int c = 0; c < 5; c++)
                    gg[c] = gumbel_from_bits(jax_bits32(key, gbase + c));
                const float* lq = &sLq[k * 25 + l * 5];
                float best = lq[0] + gg[0];
                int bi = 0;
#pragma unroll
                for (int c = 1; c < 5; c++) {
                    float sc = lq[c] + gg[c];
                    if (sc > best) { best = sc; bi = c; }
                }
                l = bi;
                lab[k * 4096 + lo0] = (unsigned char)l;
                lab[k * 4096 + lo1] = (unsigned char)l;
            }
        } else {
#pragma unroll 2
            for (int k = 0; k < N_STEPS; k++) {
                lab[k * 4096 + lo0] = 0xFFu;
                lab[k * 4096 + lo1] = 0xFFu;
            }
        }
    } else {
        // ------------------------- node chains ------------------------------
        int t = (blockIdx.x - 504) * 128 + threadIdx.x;  // 0..2047
        int b = t >> 6, i = t & 63;
        bool valid = mask_val(maskp, mode, b * 64 + i);
        uint32_t gbase = (uint32_t)((b * 64 + i) * 8);

        float in[8];
        const float* xp = X + (size_t)(b * 64 + i) * 8;
#pragma unroll
        for (int c = 0; c < 8; c++) in[c] = xp[c];

        float* postX = out + (size_t)b * 50 * 512 + (size_t)i * 8;
        float* preX  = out + OFF_XC + (size_t)b * 50 * 512 + (size_t)i * 8;

        if (valid) {
            int l = 0;
            float bv = in[0];
#pragma unroll
            for (int c = 1; c < 8; c++) if (in[c] > bv) { bv = in[c]; l = c; }
#pragma unroll 1
            for (int k = 0; k < N_STEPS; k++) {
                float* pp = preX  + (size_t)k * 512;
                float* sp = postX + (size_t)k * 512;
                if (k == 0) {
#pragma unroll
                    for (int c = 0; c < 8; c++) pp[c] = in[c];
                } else {
#pragma unroll
                    for (int c = 0; c < 8; c++) pp[c] = (c == l) ? 1.0f : 0.0f;
                }
                uint2 key = sKey[k];
                const float* lq = &sLq[k * 64 + l * 8];
                float best = 0.0f;
                int bi = 0;
#pragma unroll
                for (int c = 0; c < 8; c++) {
                    float gv = gumbel_from_bits(jax_bits32(key, gbase + c));
                    float sc = lq[c] + gv;
                    if (c == 0) best = sc;
                    else if (sc > best) { best = sc; bi = c; }
                }
                l = bi;
#pragma unroll
                for (int c = 0; c < 8; c++) sp[c] = (c == l) ? 1.0f : 0.0f;
            }
        } else {
#pragma unroll 2
            for (int k = 0; k < N_STEPS; k++) {
                float* pp = preX  + (size_t)k * 512;
                float* sp = postX + (size_t)k * 512;
#pragma unroll
                for (int c = 0; c < 8; c++) pp[c] = (k == 0) ? in[c] : 0.0f;
#pragma unroll
                for (int c = 0; c < 8; c++) sp[c] = 0.0f;
            }
        }
    }
}

// --------------------------- expansion kernel -------------------------------
// One float4 of the E post-array per thread (flat over 32*50*64*80).
// Each thread: expand labels -> one-hot float4, store post[b][k][i] row chunk,
// and store the SAME value as pre[b][k+1][i] (pre[k+1] == post[k]); threads
// with k==49 instead store pre[b][0][i] = raw E (the only pre slab that is
// not a post slab). Diagonal cells (j == i) force label 0xFF -> zeros.
__global__ __launch_bounds__(256)
void expand_kernel(const float* __restrict__ E, float* __restrict__ out) {
    int flat = blockIdx.x * 256 + threadIdx.x;
    if (flat >= N_EFLOAT4) return;
    int s = flat / 80;               // (b*50+k)*64 + i   (0..102399)
    int q = flat - s * 80;           // float4 within 320-float row
    int i = s & 63;
    int bk = s >> 6;                 // b*50 + k
    int k = bk % 50;

    const unsigned char* labRow = g_lab + (size_t)s * 64;  // = [b][k][i][*]
    int f0 = q * 4;
    float4 v;
    {
        float* vp = &v.x;
#pragma unroll
        for (int t = 0; t < 4; t++) {
            int f = f0 + t;
            int cl = f / 5;                  // j coordinate
            int ch = f - cl * 5;             // class index
            int L = (cl == i) ? 255 : (int)labRow[cl];
            vp[t] = (ch == L) ? 1.0f : 0.0f;
        }
    }
    *(float4*)(out + OFF_EN + (size_t)s * 320 + f0) = v;
    if (k < 49) {
        *(float4*)(out + OFF_EC + (size_t)(s + 64) * 320 + f0) = v;
    } else {
        int b = bk / 50;
        int s0 = s - 49 * 64;                // (b*50+0)*64 + i
        float4 raw = *(const float4*)(E + (size_t)b * 20480 + (size_t)i * 320 + f0);
        *(float4*)(out + OFF_EC + (size_t)s0 * 320 + f0) = raw;
    }
}

extern "C" void kernel_launch(void* const* d_in, const int* in_sizes, int n_in,
                              void* d_out, int out_size) {
    (void)in_sizes; (void)n_in; (void)out_size;
    const float* X      = (const float*)d_in[0];
    const float* E      = (const float*)d_in[1];
    const void*  maskp  = d_in[2];
    const float* gammas = (const float*)d_in[3];
    const float* Wx     = (const float*)d_in[4];
    const float* We     = (const float*)d_in[5];
    float* out = (float*)d_out;

    init_kernel<<<1, 256>>>(gammas, Wx, We);
    // 504 edge blocks (64512 pair chains) + 16 node blocks (2048 chains)
    chain_kernel<<<520, 128>>>(X, E, maskp, out);
    // 8,192,000 float4 / 256 = 32000 blocks
    expand_kernel<<<32000, 256>>>(E, out);
}